// round 6
// baseline (speedup 1.0000x reference)
#include <cuda_runtime.h>

#define S_LEN   2048
#define E_DIM   1024
#define NHEADS  16
#define HD      64
#define MAXR    2049   // ns rows + 1 virtual row (xsum -> vtot)
#define KSPLIT  16     // proj K-splits (64 k each)
#define RCAP    128    // rows covered by the split partial-buffer path
#define XS      32     // colsum row splits
#define ASTR    260    // proj A-dup smem row stride (floats), keeps rows 16B-aligned
#define KTSTR   132    // attn smem row stride (floats), 16B-aligned

// ---------------- device scratch (static, no runtime allocation) ----------------
__device__ int   g_lo, g_ns;
__device__ float g_xsump[XS][E_DIM];
__device__ float g_qp[KSPLIT][RCAP * E_DIM];
__device__ float g_kp[KSPLIT][RCAP * E_DIM];
__device__ float g_vp[KSPLIT][RCAP * E_DIM];
__device__ float g_q[MAXR * E_DIM];
__device__ float g_k[MAXR * E_DIM];
__device__ float g_v[MAXR * E_DIM];   // row ns = vtot
__device__ float g_att[E_DIM];        // mean attention output (pre-Wo)

// ---------------- f32x2 packed helpers ----------------
__device__ __forceinline__ void upk2(unsigned long long v, float& lo, float& hi) {
    asm("mov.b64 {%0,%1}, %2;" : "=f"(lo), "=f"(hi) : "l"(v));
}
__device__ __forceinline__ void ffma2(unsigned long long& d, unsigned long long a,
                                      unsigned long long b) {
    asm("fma.rn.f32x2 %0, %1, %2, %0;" : "+l"(d) : "l"(a), "l"(b));
}

// ---------------- K0: colsum partials + bounds + zero dout ----------------
__global__ void __launch_bounds__(256) k_pre(const float* __restrict__ x,
                                             const int* __restrict__ seg,
                                             const int* __restrict__ pos,
                                             float* __restrict__ dout) {
    int bx = blockIdx.x, by = blockIdx.y;
    int tid = threadIdx.x;
    int c  = bx * 256 + tid;
    int r0 = by * (S_LEN / XS);
    float a = 0.f;
#pragma unroll 16
    for (int r = r0; r < r0 + S_LEN / XS; ++r) a += x[(size_t)r * E_DIM + c];
    g_xsump[by][c] = a;
    if (by == 0) dout[bx * 256 + tid] = 0.f;
    if (by == 0 && bx == 0) {
        __shared__ int s_lo, s_cnt, s_t;
        if (tid == 0) { s_t = seg[pos[0]]; s_lo = 0; s_cnt = 0; }
        __syncthreads();
        int t = s_t, lo = 0, cnt = 0;
        for (int i = tid; i < S_LEN; i += 256) {
            int v = seg[i];
            lo  += (v <  t);
            cnt += (v == t);
        }
        atomicAdd(&s_lo, lo);
        atomicAdd(&s_cnt, cnt);
        __syncthreads();
        if (tid == 0) { g_lo = s_lo; g_ns = s_cnt; }
    }
}

// ---------------- proj helpers ----------------
__device__ __forceinline__ float4 proj_ldA(const float* __restrict__ x,
                                           int lo, int ns, int mat, int gr, int kidx) {
    if (gr < ns) return *(const float4*)&x[(size_t)(lo + gr) * E_DIM + kidx];
    if (gr == ns && mat == 2) {
        float4 s = make_float4(0.f, 0.f, 0.f, 0.f);
#pragma unroll
        for (int p = 0; p < XS; p++) {
            float4 t = *(const float4*)&g_xsump[p][kidx];
            s.x += t.x; s.y += t.y; s.z += t.z; s.w += t.w;
        }
        return s;
    }
    return make_float4(0.f, 0.f, 0.f, 0.f);
}

// tile worker: M = 8*R rows, N = 128 cols, K = 64 (one split), full preload
template<int R>
__device__ __forceinline__ void proj_run(
    const float* __restrict__ x, const float* __restrict__ W,
    const float* __restrict__ bias, float* __restrict__ outp,
    int lo, int ns, int nrows, int mat, int kbase, bool addBias,
    float* As_d, float* Bs, int colbase)
{
    int tid = threadIdx.x;
    int tx = tid & 31, ty = tid >> 5;
    // preload B [64 k][128 cols]  (8 float4 per thread, MLP 8)
#pragma unroll
    for (int u = 0; u < 8; u++) {
        int idx = tid + 256 * u;
        int r = idx >> 5, c4 = idx & 31;
        *(float4*)&Bs[r * 128 + c4 * 4] =
            *(const float4*)&W[(size_t)(kbase + r) * E_DIM + colbase + c4 * 4];
    }
    // preload A duplicated-pairs: As_d[k][2r] = As_d[k][2r+1] = a[r][k]
#pragma unroll
    for (int u = 0; u < R / 2; u++) {
        int idx = tid + 256 * u;
        int r = idx >> 4, k4 = idx & 15;
        float4 v = proj_ldA(x, lo, ns, mat, r, kbase + 4 * k4);
        float vv[4] = {v.x, v.y, v.z, v.w};
#pragma unroll
        for (int i = 0; i < 4; i++) {
            float2 d2; d2.x = vv[i]; d2.y = vv[i];
            *(float2*)&As_d[(4 * k4 + i) * ASTR + 2 * r] = d2;
        }
    }
    __syncthreads();

    unsigned long long acc[R][2];
#pragma unroll
    for (int r = 0; r < R; r++) { acc[r][0] = 0ULL; acc[r][1] = 0ULL; }

#pragma unroll 4
    for (int kk = 0; kk < 64; kk++) {
        const ulonglong2* ap = (const ulonglong2*)&As_d[kk * ASTR + 2 * R * ty];
        unsigned long long b0 = *(const unsigned long long*)&Bs[kk * 128 + 2 * tx];
        unsigned long long b1 = *(const unsigned long long*)&Bs[kk * 128 + 2 * tx + 64];
#pragma unroll
        for (int q = 0; q < R / 2; q++) {
            ulonglong2 t = ap[q];
            ffma2(acc[2 * q][0],     t.x, b0); ffma2(acc[2 * q][1],     t.x, b1);
            ffma2(acc[2 * q + 1][0], t.y, b0); ffma2(acc[2 * q + 1][1], t.y, b1);
        }
    }
    // epilogue: STG.64 col-pairs
#pragma unroll
    for (int r = 0; r < R; r++) {
        int gr = R * ty + r;
        if (gr >= nrows) continue;
        bool virt = (gr == ns) && (mat == 2);
#pragma unroll
        for (int p = 0; p < 2; p++) {
            float v0, v1;
            upk2(acc[r][p], v0, v1);
            int c0 = colbase + 2 * tx + 64 * p;
            if (addBias) {
                float sc = virt ? (float)S_LEN : 1.f;
                v0 += sc * bias[c0];
                v1 += sc * bias[c0 + 1];
            }
            float2 st2; st2.x = v0; st2.y = v1;
            *(float2*)&outp[(size_t)gr * E_DIM + c0] = st2;
        }
    }
}

// ---------------- K2: projections (split-K into partial buffers) ----------------
// grid (8 coltiles x128, KSPLIT, 3 mats), 256 threads, dynamic smem
__global__ void __launch_bounds__(256) k_proj(
    const float* __restrict__ x,
    const float* __restrict__ W0, const float* __restrict__ W1,
    const float* __restrict__ W2,
    const float* __restrict__ b0, const float* __restrict__ b1,
    const float* __restrict__ b2) {
    extern __shared__ float sm[];
    float* As_d = sm;               // [64][ASTR]
    float* Bs   = sm + 64 * ASTR;   // [64][128]
    int mat = blockIdx.z, kb = blockIdx.y;
    int ns = g_ns, lo = g_lo;
    int nrows = ns + (mat == 2 ? 1 : 0);
    const float* W    = (mat == 0) ? W0 : ((mat == 1) ? W1 : W2);
    const float* bias = (mat == 0) ? b0 : ((mat == 1) ? b1 : b2);
    float* partial = (mat == 0) ? g_qp[kb] : ((mat == 1) ? g_kp[kb] : g_vp[kb]);
    float* dense   = (mat == 0) ? g_q : ((mat == 1) ? g_k : g_v);
    int colbase = blockIdx.x * 128;
    int kbase = kb * 64;
    int mrows = min(nrows, RCAP);

    if      (mrows <= 64) proj_run<8>(x, W, bias, partial, lo, ns, mrows, mat, kbase, kb == 0, As_d, Bs, colbase);
    else if (mrows <= 80) proj_run<10>(x, W, bias, partial, lo, ns, mrows, mat, kbase, kb == 0, As_d, Bs, colbase);
    else if (mrows <= 96) proj_run<12>(x, W, bias, partial, lo, ns, mrows, mat, kbase, kb == 0, As_d, Bs, colbase);
    else                  proj_run<16>(x, W, bias, partial, lo, ns, mrows, mat, kbase, kb == 0, As_d, Bs, colbase);

    // rare overflow: rows >= RCAP computed dense (full K) by kb==0 blocks
    if (nrows > RCAP && kb == 0) {
        for (int idx = threadIdx.x; idx < (nrows - RCAP) * 128; idx += 256) {
            int r = RCAP + idx / 128, c = colbase + (idx & 127);
            float acc = bias[c] * ((r == ns && mat == 2) ? (float)S_LEN : 1.f);
            for (int k = 0; k < E_DIM; k++) {
                float xv;
                if (r < ns) xv = x[(size_t)(lo + r) * E_DIM + k];
                else { xv = 0.f; for (int p = 0; p < XS; p++) xv += g_xsump[p][k]; }
                acc += xv * W[(size_t)k * E_DIM + c];
            }
            dense[(size_t)r * E_DIM + c] = acc;
        }
    }
}

// ---------------- K2b: sum split-K partials (float4, high MLP) ----------------
__global__ void __launch_bounds__(256) k_reduce() {
    int ns = g_ns;
    int total = min(ns + 1, RCAP) * E_DIM;
    int base = blockIdx.x * 1024 + threadIdx.x * 4;
    if (base >= total) return;
    int arr = blockIdx.y;
    const float* src = (arr == 0) ? &g_qp[0][0] : ((arr == 1) ? &g_kp[0][0] : &g_vp[0][0]);
    float* dst = (arr == 0) ? g_q : ((arr == 1) ? g_k : g_v);
    float4 s = make_float4(0.f, 0.f, 0.f, 0.f);
#pragma unroll
    for (int p = 0; p < KSPLIT; p++) {
        float4 t = *(const float4*)&src[(size_t)p * (RCAP * E_DIM) + base];
        s.x += t.x; s.y += t.y; s.z += t.z; s.w += t.w;
    }
    *(float4*)&dst[base] = s;
}

// ---------------- attn score GEMM fragment: 64 rows x 128 cols, thread 4x8 ----------------
__device__ __forceinline__ void attn_gemm(const float* qd, const float* kt,
                                          float* s_sm, int a, int b) {
    unsigned long long acc[4][4];
#pragma unroll
    for (int r = 0; r < 4; r++)
#pragma unroll
        for (int p = 0; p < 4; p++) acc[r][p] = 0ULL;
#pragma unroll 4
    for (int dd = 0; dd < 64; dd++) {
        ulonglong2 q01 = *(const ulonglong2*)&qd[dd * KTSTR + 8 * a];
        ulonglong2 q23 = *(const ulonglong2*)&qd[dd * KTSTR + 8 * a + 4];
        ulonglong2 k01 = *(const ulonglong2*)&kt[dd * KTSTR + 8 * b];
        ulonglong2 k23 = *(const ulonglong2*)&kt[dd * KTSTR + 8 * b + 4];
        ffma2(acc[0][0], q01.x, k01.x); ffma2(acc[0][1], q01.x, k01.y);
        ffma2(acc[0][2], q01.x, k23.x); ffma2(acc[0][3], q01.x, k23.y);
        ffma2(acc[1][0], q01.y, k01.x); ffma2(acc[1][1], q01.y, k01.y);
        ffma2(acc[1][2], q01.y, k23.x); ffma2(acc[1][3], q01.y, k23.y);
        ffma2(acc[2][0], q23.x, k01.x); ffma2(acc[2][1], q23.x, k01.y);
        ffma2(acc[2][2], q23.x, k23.x); ffma2(acc[2][3], q23.x, k23.y);
        ffma2(acc[3][0], q23.y, k01.x); ffma2(acc[3][1], q23.y, k01.y);
        ffma2(acc[3][2], q23.y, k23.x); ffma2(acc[3][3], q23.y, k23.y);
    }
#pragma unroll
    for (int r = 0; r < 4; r++) {
        float4 f0, f1;
        upk2(acc[r][0], f0.x, f0.y); upk2(acc[r][1], f0.z, f0.w);
        upk2(acc[r][2], f1.x, f1.y); upk2(acc[r][3], f1.z, f1.w);
        *(float4*)&s_sm[(4 * a + r) * KTSTR + 8 * b]     = f0;
        *(float4*)&s_sm[(4 * a + r) * KTSTR + 8 * b + 4] = f1;
    }
}

// ---------------- K3: per-head attention -> g_att ----------------
// one block per head, 256 threads, dynamic smem
__global__ void __launch_bounds__(256) k_attn() {
    extern __shared__ float sm[];
    float* qd    = sm;                     // [64][KTSTR] q rows duplicated-pairs
    float* kt    = sm + 64 * KTSTR;        // [64][KTSTR] k transposed
    float* s_sm  = sm + 2 * 64 * KTSTR;    // [64][KTSTR] scores / probs
    float* c_acc = sm + 3 * 64 * KTSTR;    // [S_LEN]
    float* m_sm  = c_acc + S_LEN;          // [64]
    float* z_sm  = m_sm + 64;              // [64]
    float* red   = z_sm + 64;              // [4][64]
    float* w0p   = red + 256;              // [1]

    int h = blockIdx.x;
    int ns = g_ns;
    int tid = threadIdx.x, lane = tid & 31, w = tid >> 5;
    int zc = S_LEN - ns;
    const float* qg = g_q + h * HD;
    const float* kg = g_k + h * HD;
    int a = tid >> 4, b = tid & 15;

    for (int i = tid; i < ns; i += 256) c_acc[i] = 0.f;
    if (tid == 0) *w0p = 0.f;

    int nrt = (ns + 63) >> 6;
    int nct = (ns + 127) >> 7;

    for (int rt = 0; rt < nrt; rt++) {
        int rcnt = min(64, ns - rt * 64);
        __syncthreads();
        // load q rows for this tile, duplicated
        for (int idx = tid; idx < rcnt * HD; idx += 256) {
            int i = idx >> 6, dd = idx & 63;
            float v = qg[(size_t)(rt * 64 + i) * E_DIM + dd];
            float2 d2; d2.x = v; d2.y = v;
            *(float2*)&qd[dd * KTSTR + 2 * i] = d2;
        }
        if (nct == 1) {
            if (rt == 0)
                for (int idx = tid; idx < ns * HD; idx += 256) {
                    int j = idx >> 6, dd = idx & 63;
                    kt[dd * KTSTR + j] = kg[(size_t)j * E_DIM + dd];
                }
            __syncthreads();
            attn_gemm(qd, kt, s_sm, a, b);
            __syncthreads();
            // stats + transform in place, warp per row
            for (int t = 0; t < 8; t++) {
                int i = t * 8 + w;
                if (i >= rcnt) break;
                float m = -1e30f;
                for (int j = lane; j < ns; j += 32) m = fmaxf(m, s_sm[i * KTSTR + j]);
#pragma unroll
                for (int o = 16; o > 0; o >>= 1)
                    m = fmaxf(m, __shfl_xor_sync(0xffffffffu, m, o));
                if (zc > 0) m = fmaxf(m, 0.f);        // masked entries are ZERO, not -inf
                float Z = 0.f;
                for (int j = lane; j < ns; j += 32) Z += __expf(s_sm[i * KTSTR + j] - m);
#pragma unroll
                for (int o = 16; o > 0; o >>= 1)
                    Z += __shfl_xor_sync(0xffffffffu, Z, o);
                Z += (float)zc * __expf(-m);
                float invZ = 1.f / Z;
                for (int j = lane; j < ns; j += 32)
                    s_sm[i * KTSTR + j] = __expf(s_sm[i * KTSTR + j] - m) * invZ;
                if (lane == 0) atomicAdd(w0p, __expf(-m) * invZ);
            }
            __syncthreads();
            for (int j = tid; j < ns; j += 256) {
                float s = 0.f;
                for (int r = 0; r < rcnt; r++) s += s_sm[r * KTSTR + j];
                c_acc[j] += s;
            }
        } else {
            // general path (ns > 128): two passes with online stats
            if (tid < 64) { m_sm[tid] = -1e30f; z_sm[tid] = 0.f; }
            for (int ct = 0; ct < nct; ct++) {
                int cl = min(128, ns - ct * 128);
                __syncthreads();
                for (int idx = tid; idx < cl * HD; idx += 256) {
                    int j = idx >> 6, dd = idx & 63;
                    kt[dd * KTSTR + j] = kg[(size_t)(ct * 128 + j) * E_DIM + dd];
                }
                __syncthreads();
                attn_gemm(qd, kt, s_sm, a, b);
                __syncthreads();
                for (int t = 0; t < 8; t++) {
                    int i = t * 8 + w;
                    if (i >= rcnt) break;
                    float tm = -1e30f;
                    for (int j = lane; j < cl; j += 32) tm = fmaxf(tm, s_sm[i * KTSTR + j]);
#pragma unroll
                    for (int o = 16; o > 0; o >>= 1)
                        tm = fmaxf(tm, __shfl_xor_sync(0xffffffffu, tm, o));
                    float tz = 0.f;
                    for (int j = lane; j < cl; j += 32) tz += __expf(s_sm[i * KTSTR + j] - tm);
#pragma unroll
                    for (int o = 16; o > 0; o >>= 1)
                        tz += __shfl_xor_sync(0xffffffffu, tz, o);
                    if (lane == 0) {
                        float mo = m_sm[i], zo = z_sm[i];
                        float mn = fmaxf(mo, tm);
                        z_sm[i] = zo * __expf(mo - mn) + tz * __expf(tm - mn);
                        m_sm[i] = mn;
                    }
                }
            }
            __syncthreads();
            if (tid < rcnt) {
                float m = m_sm[tid];
                if (zc > 0) m = fmaxf(m, 0.f);
                float z = z_sm[tid] * __expf(m_sm[tid] - m) + (float)zc * __expf(-m);
                m_sm[tid] = m;
                z_sm[tid] = 1.f / z;
                atomicAdd(w0p, __expf(-m) / z);
            }
            for (int ct = 0; ct < nct; ct++) {
                int cl = min(128, ns - ct * 128);
                __syncthreads();
                for (int idx = tid; idx < cl * HD; idx += 256) {
                    int j = idx >> 6, dd = idx & 63;
                    kt[dd * KTSTR + j] = kg[(size_t)(ct * 128 + j) * E_DIM + dd];
                }
                __syncthreads();
                attn_gemm(qd, kt, s_sm, a, b);
                __syncthreads();
                for (int j = tid; j < cl; j += 256) {
                    float s = 0.f;
                    for (int r = 0; r < rcnt; r++)
                        s += __expf(s_sm[r * KTSTR + j] - m_sm[r]) * z_sm[r];
                    c_acc[ct * 128 + j] += s;
                }
            }
        }
    }
    __syncthreads();
    // weighted V column-sum -> mean attention output
    int d = tid & 63, grp = tid >> 6;
    float w0 = *w0p;
    float acc4 = 0.f;
    for (int j = grp; j < ns; j += 4)
        acc4 += (c_acc[j] - w0) * g_v[(size_t)j * E_DIM + h * HD + d];
    red[grp * 64 + d] = acc4;
    __syncthreads();
    if (tid < 64) {
        float tot = red[d] + red[64 + d] + red[128 + d] + red[192 + d]
                  + w0 * g_v[(size_t)ns * E_DIM + h * HD + d];   // vtot row
        g_att[h * HD + d] = tot / (float)ns;
    }
}

// ---------------- K4: final vecmat out = att @ Wo + bo (split-K x32) ----------------
__global__ void __launch_bounds__(256) k_out(const float* __restrict__ Wo,
                                             const float* __restrict__ bo,
                                             float* __restrict__ dout) {
    int ky = blockIdx.y;
    int k0 = ky * 32;
    __shared__ float a_s[32];
    if (threadIdx.x < 32) a_s[threadIdx.x] = g_att[k0 + threadIdx.x];
    __syncthreads();
    int c = blockIdx.x * 256 + threadIdx.x;
    float acc = (ky == 0) ? bo[c] : 0.f;
#pragma unroll
    for (int kk = 0; kk < 32; kk++)
        acc += a_s[kk] * Wo[(size_t)(k0 + kk) * E_DIM + c];
    atomicAdd(&dout[c], acc);
}

// ---------------- launch ----------------
#define PROJ_SMEM ((64 * ASTR + 64 * 128) * 4)
#define ATTN_SMEM ((3 * 64 * KTSTR + S_LEN + 64 + 64 + 256 + 4) * 4)

extern "C" void kernel_launch(void* const* d_in, const int* in_sizes, int n_in,
                              void* d_out, int out_size) {
    const float* x   = (const float*)d_in[0];
    const int*   seg = (const int*)d_in[1];
    const int*   pos = (const int*)d_in[2];
    const float* Wq = (const float*)d_in[3];
    const float* bq = (const float*)d_in[4];
    const float* Wk = (const float*)d_in[5];
    const float* bk = (const float*)d_in[6];
    const float* Wv = (const float*)d_in[7];
    const float* bv = (const float*)d_in[8];
    const float* Wo = (const float*)d_in[9];
    const float* bo = (const float*)d_in[10];
    float* out = (float*)d_out;

    static int attr_done = 0;
    if (!attr_done) {
        cudaFuncSetAttribute(k_proj, cudaFuncAttributeMaxDynamicSharedMemorySize, PROJ_SMEM);
        cudaFuncSetAttribute(k_attn, cudaFuncAttributeMaxDynamicSharedMemorySize, ATTN_SMEM);
        attr_done = 1;
    }

    k_pre<<<dim3(4, XS), 256>>>(x, seg, pos, out);
    k_proj<<<dim3(8, KSPLIT, 3), 256, PROJ_SMEM>>>(x, Wq, Wk, Wv, bq, bk, bv);
    k_reduce<<<dim3(RCAP, 3), 256>>>();
    k_attn<<<NHEADS, 256, ATTN_SMEM>>>();
    k_out<<<dim3(4, 32), 256>>>(Wo, bo, out);
}

// round 7
// speedup vs baseline: 1.1244x; 1.1244x over previous
#include <cuda_runtime.h>

#define S_LEN   2048
#define E_DIM   1024
#define NHEADS  16
#define HD      64
#define MAXR    2049   // ns rows + 1 virtual row (xsum -> vtot)
#define KSPLIT  16     // proj K-splits (64 k each)
#define RCAP    128    // rows covered by the split partial-buffer path
#define XS      32     // colsum row splits
#define ASTR    260    // proj A-dup smem row stride (floats)
#define KBSTR   68     // attn smem row stride (floats); 68/4=17 odd -> conflict-free float4

// ---------------- device scratch (static, no runtime allocation) ----------------
__device__ int   g_lo, g_ns;
__device__ float g_xsump[XS][E_DIM];
__device__ float g_qp[KSPLIT][RCAP * E_DIM];
__device__ float g_kp[KSPLIT][RCAP * E_DIM];
__device__ float g_vp[KSPLIT][RCAP * E_DIM];
__device__ float g_q[MAXR * E_DIM];
__device__ float g_k[MAXR * E_DIM];
__device__ float g_v[MAXR * E_DIM];   // row ns = vtot
__device__ float g_att[E_DIM];        // mean attention output (pre-Wo)

// ---------------- f32x2 packed helpers ----------------
__device__ __forceinline__ void upk2(unsigned long long v, float& lo, float& hi) {
    asm("mov.b64 {%0,%1}, %2;" : "=f"(lo), "=f"(hi) : "l"(v));
}
__device__ __forceinline__ void ffma2(unsigned long long& d, unsigned long long a,
                                      unsigned long long b) {
    asm("fma.rn.f32x2 %0, %1, %2, %0;" : "+l"(d) : "l"(a), "l"(b));
}

// ---------------- K0: colsum partials + bounds + zero dout ----------------
__global__ void __launch_bounds__(256) k_pre(const float* __restrict__ x,
                                             const int* __restrict__ seg,
                                             const int* __restrict__ pos,
                                             float* __restrict__ dout) {
    int bx = blockIdx.x, by = blockIdx.y;
    int tid = threadIdx.x;
    int c  = bx * 256 + tid;
    int r0 = by * (S_LEN / XS);
    float a = 0.f;
#pragma unroll 16
    for (int r = r0; r < r0 + S_LEN / XS; ++r) a += x[(size_t)r * E_DIM + c];
    g_xsump[by][c] = a;
    if (by == 0) dout[bx * 256 + tid] = 0.f;
    if (by == 0 && bx == 0) {
        __shared__ int s_lo, s_cnt, s_t;
        if (tid == 0) { s_t = seg[pos[0]]; s_lo = 0; s_cnt = 0; }
        __syncthreads();
        int t = s_t, lo = 0, cnt = 0;
        for (int i = tid; i < S_LEN; i += 256) {
            int v = seg[i];
            lo  += (v <  t);
            cnt += (v == t);
        }
        atomicAdd(&s_lo, lo);
        atomicAdd(&s_cnt, cnt);
        __syncthreads();
        if (tid == 0) { g_lo = s_lo; g_ns = s_cnt; }
    }
}

// ---------------- proj helpers ----------------
__device__ __forceinline__ float4 proj_ldA(const float* __restrict__ x,
                                           int lo, int ns, int mat, int gr, int kidx) {
    if (gr < ns) return *(const float4*)&x[(size_t)(lo + gr) * E_DIM + kidx];
    if (gr == ns && mat == 2) {
        float4 s = make_float4(0.f, 0.f, 0.f, 0.f);
#pragma unroll
        for (int p = 0; p < XS; p++) {
            float4 t = *(const float4*)&g_xsump[p][kidx];
            s.x += t.x; s.y += t.y; s.z += t.z; s.w += t.w;
        }
        return s;
    }
    return make_float4(0.f, 0.f, 0.f, 0.f);
}

// tile worker: M = 8*R rows, N = 128 cols, K = 64 (one split), full preload
template<int R>
__device__ __forceinline__ void proj_run(
    const float* __restrict__ x, const float* __restrict__ W,
    const float* __restrict__ bias, float* __restrict__ outp,
    int lo, int ns, int nrows, int mat, int kbase, bool addBias,
    float* As_d, float* Bs, int colbase)
{
    int tid = threadIdx.x;
    int tx = tid & 31, ty = tid >> 5;
#pragma unroll
    for (int u = 0; u < 8; u++) {
        int idx = tid + 256 * u;
        int r = idx >> 5, c4 = idx & 31;
        *(float4*)&Bs[r * 128 + c4 * 4] =
            *(const float4*)&W[(size_t)(kbase + r) * E_DIM + colbase + c4 * 4];
    }
#pragma unroll
    for (int u = 0; u < R / 2; u++) {
        int idx = tid + 256 * u;
        int r = idx >> 4, k4 = idx & 15;
        float4 v = proj_ldA(x, lo, ns, mat, r, kbase + 4 * k4);
        float vv[4] = {v.x, v.y, v.z, v.w};
#pragma unroll
        for (int i = 0; i < 4; i++) {
            float2 d2; d2.x = vv[i]; d2.y = vv[i];
            *(float2*)&As_d[(4 * k4 + i) * ASTR + 2 * r] = d2;
        }
    }
    __syncthreads();

    unsigned long long acc[R][2];
#pragma unroll
    for (int r = 0; r < R; r++) { acc[r][0] = 0ULL; acc[r][1] = 0ULL; }

#pragma unroll 4
    for (int kk = 0; kk < 64; kk++) {
        const ulonglong2* ap = (const ulonglong2*)&As_d[kk * ASTR + 2 * R * ty];
        unsigned long long b0 = *(const unsigned long long*)&Bs[kk * 128 + 2 * tx];
        unsigned long long b1 = *(const unsigned long long*)&Bs[kk * 128 + 2 * tx + 64];
#pragma unroll
        for (int q = 0; q < R / 2; q++) {
            ulonglong2 t = ap[q];
            ffma2(acc[2 * q][0],     t.x, b0); ffma2(acc[2 * q][1],     t.x, b1);
            ffma2(acc[2 * q + 1][0], t.y, b0); ffma2(acc[2 * q + 1][1], t.y, b1);
        }
    }
#pragma unroll
    for (int r = 0; r < R; r++) {
        int gr = R * ty + r;
        if (gr >= nrows) continue;
        bool virt = (gr == ns) && (mat == 2);
#pragma unroll
        for (int p = 0; p < 2; p++) {
            float v0, v1;
            upk2(acc[r][p], v0, v1);
            int c0 = colbase + 2 * tx + 64 * p;
            if (addBias) {
                float sc = virt ? (float)S_LEN : 1.f;
                v0 += sc * bias[c0];
                v1 += sc * bias[c0 + 1];
            }
            float2 st2; st2.x = v0; st2.y = v1;
            *(float2*)&outp[(size_t)gr * E_DIM + c0] = st2;
        }
    }
}

// ---------------- K2: projections (split-K into partial buffers) ----------------
__global__ void __launch_bounds__(256) k_proj(
    const float* __restrict__ x,
    const float* __restrict__ W0, const float* __restrict__ W1,
    const float* __restrict__ W2,
    const float* __restrict__ b0, const float* __restrict__ b1,
    const float* __restrict__ b2) {
    extern __shared__ float sm[];
    float* As_d = sm;               // [64][ASTR]
    float* Bs   = sm + 64 * ASTR;   // [64][128]
    int mat = blockIdx.z, kb = blockIdx.y;
    int ns = g_ns, lo = g_lo;
    int nrows = ns + (mat == 2 ? 1 : 0);
    const float* W    = (mat == 0) ? W0 : ((mat == 1) ? W1 : W2);
    const float* bias = (mat == 0) ? b0 : ((mat == 1) ? b1 : b2);
    float* partial = (mat == 0) ? g_qp[kb] : ((mat == 1) ? g_kp[kb] : g_vp[kb]);
    float* dense   = (mat == 0) ? g_q : ((mat == 1) ? g_k : g_v);
    int colbase = blockIdx.x * 128;
    int kbase = kb * 64;
    int mrows = min(nrows, RCAP);

    if      (mrows <= 64) proj_run<8>(x, W, bias, partial, lo, ns, mrows, mat, kbase, kb == 0, As_d, Bs, colbase);
    else if (mrows <= 80) proj_run<10>(x, W, bias, partial, lo, ns, mrows, mat, kbase, kb == 0, As_d, Bs, colbase);
    else if (mrows <= 96) proj_run<12>(x, W, bias, partial, lo, ns, mrows, mat, kbase, kb == 0, As_d, Bs, colbase);
    else                  proj_run<16>(x, W, bias, partial, lo, ns, mrows, mat, kbase, kb == 0, As_d, Bs, colbase);

    if (nrows > RCAP && kb == 0) {
        for (int idx = threadIdx.x; idx < (nrows - RCAP) * 128; idx += 256) {
            int r = RCAP + idx / 128, c = colbase + (idx & 127);
            float acc = bias[c] * ((r == ns && mat == 2) ? (float)S_LEN : 1.f);
            for (int k = 0; k < E_DIM; k++) {
                float xv;
                if (r < ns) xv = x[(size_t)(lo + r) * E_DIM + k];
                else { xv = 0.f; for (int p = 0; p < XS; p++) xv += g_xsump[p][k]; }
                acc += xv * W[(size_t)k * E_DIM + c];
            }
            dense[(size_t)r * E_DIM + c] = acc;
        }
    }
}

// ---------------- K2b: sum split-K partials (float4, high MLP) ----------------
__global__ void __launch_bounds__(256) k_reduce() {
    int ns = g_ns;
    int total = min(ns + 1, RCAP) * E_DIM;
    int base = blockIdx.x * 1024 + threadIdx.x * 4;
    if (base >= total) return;
    int arr = blockIdx.y;
    const float* src = (arr == 0) ? &g_qp[0][0] : ((arr == 1) ? &g_kp[0][0] : &g_vp[0][0]);
    float* dst = (arr == 0) ? g_q : ((arr == 1) ? g_k : g_v);
    float4 s = make_float4(0.f, 0.f, 0.f, 0.f);
#pragma unroll
    for (int p = 0; p < KSPLIT; p++) {
        float4 t = *(const float4*)&src[(size_t)p * (RCAP * E_DIM) + base];
        s.x += t.x; s.y += t.y; s.z += t.z; s.w += t.w;
    }
    *(float4*)&dst[base] = s;
}

// ---------------- K3: per-head attention (vectorized dots, cached scores) ----------------
// one block per head, 512 threads (16 warps, warp per row)
__global__ void __launch_bounds__(512) k_attn() {
    extern __shared__ float sm[];
    float* kbuf  = sm;                   // [128][KBSTR]
    float* qr    = kbuf + 128 * KBSTR;   // [16][KBSTR]
    float* c_acc = qr + 16 * KBSTR;      // [S_LEN]
    float* red   = c_acc + S_LEN;        // [8][64]
    float* w0p   = red + 512;            // [1]

    const int JT = 128;
    int h = blockIdx.x, ns = g_ns;
    int tid = threadIdx.x, w = tid >> 5, lane = tid & 31;
    const float* qh = g_q + h * HD;
    const float* kh = g_k + h * HD;

    __shared__ int s_loaded;
    if (tid == 0) { s_loaded = -1; *w0p = 0.f; }
    for (int i = tid; i < ns; i += 512) c_acc[i] = 0.f;
    __syncthreads();

    int nchunks = (ns + JT - 1) / JT;
    int ngroups = (ns + 15) / 16;
    int zc = S_LEN - ns;
    bool cacheS = (ns <= 256);

    for (int g = 0; g < ngroups; ++g) {
        int i = g * 16 + w;
        bool active = (i < ns);
        if (active && lane < 16)
            *(float4*)&qr[w * KBSTR + 4 * lane] =
                *(const float4*)&qh[(size_t)i * E_DIM + 4 * lane];
        __syncwarp();
        float sreg[8];
        float m = -1e30f, Z = 0.f;
        for (int c = 0; c < nchunks; c++) {
            int c0 = c * JT;
            int cl = min(JT, ns - c0);
            if (s_loaded != c) {
                __syncthreads();
                for (int idx = tid; idx < cl * 16; idx += 512) {
                    int j = idx >> 4, d4 = idx & 15;
                    *(float4*)&kbuf[j * KBSTR + 4 * d4] =
                        *(const float4*)&kh[(size_t)(c0 + j) * E_DIM + 4 * d4];
                }
                if (tid == 0) s_loaded = c;
                __syncthreads();
            }
            if (active) {
                const ulonglong2* qp = (const ulonglong2*)&qr[w * KBSTR];
                for (int j = lane; j < cl; j += 32) {
                    const ulonglong2* kp = (const ulonglong2*)&kbuf[j * KBSTR];
                    unsigned long long s01 = 0ULL, s23 = 0ULL;
#pragma unroll
                    for (int d4 = 0; d4 < 16; d4++) {
                        ulonglong2 qv = qp[d4];
                        ulonglong2 kv = kp[d4];
                        ffma2(s01, qv.x, kv.x);
                        ffma2(s23, qv.y, kv.y);
                    }
                    float e0, e1, e2, e3;
                    upk2(s01, e0, e1); upk2(s23, e2, e3);
                    float s = (e0 + e1) + (e2 + e3);
                    if (cacheS) sreg[(c0 + j) >> 5] = s;
                    float mn = fmaxf(m, s);
                    Z = Z * __expf(m - mn) + __expf(s - mn);
                    m = mn;
                }
            }
        }
        float mrow = 0.f, invZ = 0.f;
        if (active) {
            mrow = m;
#pragma unroll
            for (int o = 16; o > 0; o >>= 1)
                mrow = fmaxf(mrow, __shfl_xor_sync(0xffffffffu, mrow, o));
            if (zc > 0) mrow = fmaxf(mrow, 0.f);     // masked entries are ZERO, not -inf
            float z = Z * __expf(m - mrow);
#pragma unroll
            for (int o = 16; o > 0; o >>= 1)
                z += __shfl_xor_sync(0xffffffffu, z, o);
            z += (float)zc * __expf(-mrow);
            invZ = 1.f / z;
        }
        if (cacheS) {
            if (active) {
                for (int t = 0; t * 32 < ns; t++) {
                    int jc = t * 32 + lane;
                    if (jc < ns)
                        atomicAdd(&c_acc[jc], __expf(sreg[t] - mrow) * invZ);
                }
            }
        } else {
            // rare path ns > 256: recompute dots
            for (int c = 0; c < nchunks; c++) {
                int c0 = c * JT;
                int cl = min(JT, ns - c0);
                if (s_loaded != c) {
                    __syncthreads();
                    for (int idx = tid; idx < cl * 16; idx += 512) {
                        int j = idx >> 4, d4 = idx & 15;
                        *(float4*)&kbuf[j * KBSTR + 4 * d4] =
                            *(const float4*)&kh[(size_t)(c0 + j) * E_DIM + 4 * d4];
                    }
                    if (tid == 0) s_loaded = c;
                    __syncthreads();
                }
                if (active) {
                    const ulonglong2* qp = (const ulonglong2*)&qr[w * KBSTR];
                    for (int j = lane; j < cl; j += 32) {
                        const ulonglong2* kp = (const ulonglong2*)&kbuf[j * KBSTR];
                        unsigned long long s01 = 0ULL, s23 = 0ULL;
#pragma unroll
                        for (int d4 = 0; d4 < 16; d4++) {
                            ulonglong2 qv = qp[d4];
                            ulonglong2 kv = kp[d4];
                            ffma2(s01, qv.x, kv.x);
                            ffma2(s23, qv.y, kv.y);
                        }
                        float e0, e1, e2, e3;
                        upk2(s01, e0, e1); upk2(s23, e2, e3);
                        float s = (e0 + e1) + (e2 + e3);
                        atomicAdd(&c_acc[c0 + j], __expf(s - mrow) * invZ);
                    }
                }
            }
        }
        if (active && lane == 0) atomicAdd(w0p, __expf(-mrow) * invZ);
    }
    __syncthreads();

    // weighted V column-sum -> mean attention output
    int d = tid & 63, grp = tid >> 6;
    float w0 = *w0p;
    float acc = 0.f;
    for (int j = grp; j < ns; j += 8)
        acc += (c_acc[j] - w0) * g_v[(size_t)j * E_DIM + h * HD + d];
    red[grp * 64 + d] = acc;
    __syncthreads();
    if (tid < 64) {
        float tot = red[d] + red[64 + d] + red[128 + d] + red[192 + d]
                  + red[256 + d] + red[320 + d] + red[384 + d] + red[448 + d]
                  + w0 * g_v[(size_t)ns * E_DIM + h * HD + d];   // vtot row
        g_att[h * HD + d] = tot / (float)ns;
    }
}

// ---------------- K4: final vecmat out = att @ Wo + bo (split-K x32) ----------------
__global__ void __launch_bounds__(256) k_out(const float* __restrict__ Wo,
                                             const float* __restrict__ bo,
                                             float* __restrict__ dout) {
    int ky = blockIdx.y;
    int k0 = ky * 32;
    __shared__ float a_s[32];
    if (threadIdx.x < 32) a_s[threadIdx.x] = g_att[k0 + threadIdx.x];
    __syncthreads();
    int c = blockIdx.x * 256 + threadIdx.x;
    float acc = (ky == 0) ? bo[c] : 0.f;
#pragma unroll
    for (int kk = 0; kk < 32; kk++)
        acc += a_s[kk] * Wo[(size_t)(k0 + kk) * E_DIM + c];
    atomicAdd(&dout[c], acc);
}

// ---------------- launch ----------------
#define PROJ_SMEM ((64 * ASTR + 64 * 128) * 4)
#define ATTN_SMEM ((128 * KBSTR + 16 * KBSTR + S_LEN + 512 + 4) * 4)

extern "C" void kernel_launch(void* const* d_in, const int* in_sizes, int n_in,
                              void* d_out, int out_size) {
    const float* x   = (const float*)d_in[0];
    const int*   seg = (const int*)d_in[1];
    const int*   pos = (const int*)d_in[2];
    const float* Wq = (const float*)d_in[3];
    const float* bq = (const float*)d_in[4];
    const float* Wk = (const float*)d_in[5];
    const float* bk = (const float*)d_in[6];
    const float* Wv = (const float*)d_in[7];
    const float* bv = (const float*)d_in[8];
    const float* Wo = (const float*)d_in[9];
    const float* bo = (const float*)d_in[10];
    float* out = (float*)d_out;

    cudaFuncSetAttribute(k_proj, cudaFuncAttributeMaxDynamicSharedMemorySize, PROJ_SMEM);
    cudaFuncSetAttribute(k_attn, cudaFuncAttributeMaxDynamicSharedMemorySize, ATTN_SMEM);

    k_pre<<<dim3(4, XS), 256>>>(x, seg, pos, out);
    k_proj<<<dim3(8, KSPLIT, 3), 256, PROJ_SMEM>>>(x, Wq, Wk, Wv, bq, bk, bv);
    k_reduce<<<dim3(RCAP, 3), 256>>>();
    k_attn<<<NHEADS, 512, ATTN_SMEM>>>();
    k_out<<<dim3(4, 32), 256>>>(Wo, bo, out);
}

// round 8
// speedup vs baseline: 1.3433x; 1.1948x over previous
#include <cuda_runtime.h>

#define S_LEN   2048
#define E_DIM   1024
#define NHEADS  16
#define HD      64
#define MAXR    2049   // ns rows + 1 virtual row (xsum -> vtot)
#define KSPLIT  16     // proj K-splits (64 k each)
#define RCAP    128    // rows covered by the split partial-buffer path
#define XS      32     // colsum row splits
#define ASTR    260    // proj A-dup smem row stride (floats)
#define KBSTR   68     // attn smem row stride (floats); 68/4=17 odd -> conflict-free float4

// ---------------- device scratch (static, no runtime allocation) ----------------
__device__ int   g_lo, g_ns;
__device__ float g_xsump[XS][E_DIM];
__device__ float g_qp[KSPLIT][RCAP * E_DIM];
__device__ float g_kp[KSPLIT][RCAP * E_DIM];
__device__ float g_vp[KSPLIT][RCAP * E_DIM];
__device__ float g_q[MAXR * E_DIM];
__device__ float g_k[MAXR * E_DIM];
__device__ float g_v[MAXR * E_DIM];   // row ns = vtot
__device__ float g_c[NHEADS * S_LEN]; // per-head softmax column sums
__device__ float g_w0[NHEADS];
__device__ float g_att[E_DIM];        // mean attention output (pre-Wo)

// ---------------- f32x2 packed helpers ----------------
__device__ __forceinline__ void upk2(unsigned long long v, float& lo, float& hi) {
    asm("mov.b64 {%0,%1}, %2;" : "=f"(lo), "=f"(hi) : "l"(v));
}
__device__ __forceinline__ void ffma2(unsigned long long& d, unsigned long long a,
                                      unsigned long long b) {
    asm("fma.rn.f32x2 %0, %1, %2, %0;" : "+l"(d) : "l"(a), "l"(b));
}

// ---------------- K0: colsum partials + bounds + zero scratch ----------------
// grid (4, XS=32) = 128 blocks, 256 threads
__global__ void __launch_bounds__(256) k_pre(const float* __restrict__ x,
                                             const int* __restrict__ seg,
                                             const int* __restrict__ pos,
                                             float* __restrict__ dout) {
    int bx = blockIdx.x, by = blockIdx.y;
    int tid = threadIdx.x;
    int c  = bx * 256 + tid;
    int r0 = by * (S_LEN / XS);
    float a = 0.f;
#pragma unroll 16
    for (int r = r0; r < r0 + S_LEN / XS; ++r) a += x[(size_t)r * E_DIM + c];
    g_xsump[by][c] = a;
    int lb = by * 4 + bx;                        // 0..127
    g_c[lb * 256 + tid] = 0.f;                   // covers NHEADS*S_LEN = 32768
    if (by == 0) dout[bx * 256 + tid] = 0.f;
    if (lb == 0 && tid < NHEADS) g_w0[tid] = 0.f;
    if (lb == 0) {
        __shared__ int s_lo, s_cnt, s_t;
        if (tid == 0) { s_t = seg[pos[0]]; s_lo = 0; s_cnt = 0; }
        __syncthreads();
        int t = s_t, lo = 0, cnt = 0;
        for (int i = tid; i < S_LEN; i += 256) {
            int v = seg[i];
            lo  += (v <  t);
            cnt += (v == t);
        }
        atomicAdd(&s_lo, lo);
        atomicAdd(&s_cnt, cnt);
        __syncthreads();
        if (tid == 0) { g_lo = s_lo; g_ns = s_cnt; }
    }
}

// ---------------- proj helpers ----------------
__device__ __forceinline__ float4 proj_ldA(const float* __restrict__ x,
                                           int lo, int ns, int mat, int gr, int kidx) {
    if (gr < ns) return *(const float4*)&x[(size_t)(lo + gr) * E_DIM + kidx];
    if (gr == ns && mat == 2) {
        float4 s = make_float4(0.f, 0.f, 0.f, 0.f);
#pragma unroll
        for (int p = 0; p < XS; p++) {
            float4 t = *(const float4*)&g_xsump[p][kidx];
            s.x += t.x; s.y += t.y; s.z += t.z; s.w += t.w;
        }
        return s;
    }
    return make_float4(0.f, 0.f, 0.f, 0.f);
}

// tile worker: M = 8*R rows, N = 128 cols, K = 64 (one split), full preload
template<int R>
__device__ __forceinline__ void proj_run(
    const float* __restrict__ x, const float* __restrict__ W,
    const float* __restrict__ bias, float* __restrict__ outp,
    int lo, int ns, int nrows, int mat, int kbase, bool addBias,
    float* As_d, float* Bs, int colbase)
{
    int tid = threadIdx.x;
    int tx = tid & 31, ty = tid >> 5;
#pragma unroll
    for (int u = 0; u < 8; u++) {
        int idx = tid + 256 * u;
        int r = idx >> 5, c4 = idx & 31;
        *(float4*)&Bs[r * 128 + c4 * 4] =
            *(const float4*)&W[(size_t)(kbase + r) * E_DIM + colbase + c4 * 4];
    }
#pragma unroll
    for (int u = 0; u < R / 2; u++) {
        int idx = tid + 256 * u;
        int r = idx >> 4, k4 = idx & 15;
        float4 v = proj_ldA(x, lo, ns, mat, r, kbase + 4 * k4);
        float vv[4] = {v.x, v.y, v.z, v.w};
#pragma unroll
        for (int i = 0; i < 4; i++) {
            float2 d2; d2.x = vv[i]; d2.y = vv[i];
            *(float2*)&As_d[(4 * k4 + i) * ASTR + 2 * r] = d2;
        }
    }
    __syncthreads();

    unsigned long long acc[R][2];
#pragma unroll
    for (int r = 0; r < R; r++) { acc[r][0] = 0ULL; acc[r][1] = 0ULL; }

#pragma unroll 4
    for (int kk = 0; kk < 64; kk++) {
        const ulonglong2* ap = (const ulonglong2*)&As_d[kk * ASTR + 2 * R * ty];
        unsigned long long b0 = *(const unsigned long long*)&Bs[kk * 128 + 2 * tx];
        unsigned long long b1 = *(const unsigned long long*)&Bs[kk * 128 + 2 * tx + 64];
#pragma unroll
        for (int q = 0; q < R / 2; q++) {
            ulonglong2 t = ap[q];
            ffma2(acc[2 * q][0],     t.x, b0); ffma2(acc[2 * q][1],     t.x, b1);
            ffma2(acc[2 * q + 1][0], t.y, b0); ffma2(acc[2 * q + 1][1], t.y, b1);
        }
    }
#pragma unroll
    for (int r = 0; r < R; r++) {
        int gr = R * ty + r;
        if (gr >= nrows) continue;
        bool virt = (gr == ns) && (mat == 2);
#pragma unroll
        for (int p = 0; p < 2; p++) {
            float v0, v1;
            upk2(acc[r][p], v0, v1);
            int c0 = colbase + 2 * tx + 64 * p;
            if (addBias) {
                float sc = virt ? (float)S_LEN : 1.f;
                v0 += sc * bias[c0];
                v1 += sc * bias[c0 + 1];
            }
            float2 st2; st2.x = v0; st2.y = v1;
            *(float2*)&outp[(size_t)gr * E_DIM + c0] = st2;
        }
    }
}

// ---------------- K2: projections (split-K into partial buffers) ----------------
__global__ void __launch_bounds__(256) k_proj(
    const float* __restrict__ x,
    const float* __restrict__ W0, const float* __restrict__ W1,
    const float* __restrict__ W2,
    const float* __restrict__ b0, const float* __restrict__ b1,
    const float* __restrict__ b2) {
    extern __shared__ float sm[];
    float* As_d = sm;               // [64][ASTR]
    float* Bs   = sm + 64 * ASTR;   // [64][128]
    int mat = blockIdx.z, kb = blockIdx.y;
    int ns = g_ns, lo = g_lo;
    int nrows = ns + (mat == 2 ? 1 : 0);
    const float* W    = (mat == 0) ? W0 : ((mat == 1) ? W1 : W2);
    const float* bias = (mat == 0) ? b0 : ((mat == 1) ? b1 : b2);
    float* partial = (mat == 0) ? g_qp[kb] : ((mat == 1) ? g_kp[kb] : g_vp[kb]);
    float* dense   = (mat == 0) ? g_q : ((mat == 1) ? g_k : g_v);
    int colbase = blockIdx.x * 128;
    int kbase = kb * 64;
    int mrows = min(nrows, RCAP);

    if      (mrows <= 64) proj_run<8>(x, W, bias, partial, lo, ns, mrows, mat, kbase, kb == 0, As_d, Bs, colbase);
    else if (mrows <= 80) proj_run<10>(x, W, bias, partial, lo, ns, mrows, mat, kbase, kb == 0, As_d, Bs, colbase);
    else if (mrows <= 96) proj_run<12>(x, W, bias, partial, lo, ns, mrows, mat, kbase, kb == 0, As_d, Bs, colbase);
    else                  proj_run<16>(x, W, bias, partial, lo, ns, mrows, mat, kbase, kb == 0, As_d, Bs, colbase);

    if (nrows > RCAP && kb == 0) {
        for (int idx = threadIdx.x; idx < (nrows - RCAP) * 128; idx += 256) {
            int r = RCAP + idx / 128, c = colbase + (idx & 127);
            float acc = bias[c] * ((r == ns && mat == 2) ? (float)S_LEN : 1.f);
            for (int k = 0; k < E_DIM; k++) {
                float xv;
                if (r < ns) xv = x[(size_t)(lo + r) * E_DIM + k];
                else { xv = 0.f; for (int p = 0; p < XS; p++) xv += g_xsump[p][k]; }
                acc += xv * W[(size_t)k * E_DIM + c];
            }
            dense[(size_t)r * E_DIM + c] = acc;
        }
    }
}

// ---------------- K2b: sum split-K partials (float4, high MLP) ----------------
__global__ void __launch_bounds__(256) k_reduce() {
    int ns = g_ns;
    int total = min(ns + 1, RCAP) * E_DIM;
    int base = blockIdx.x * 1024 + threadIdx.x * 4;
    if (base >= total) return;
    int arr = blockIdx.y;
    const float* src = (arr == 0) ? &g_qp[0][0] : ((arr == 1) ? &g_kp[0][0] : &g_vp[0][0]);
    float* dst = (arr == 0) ? g_q : ((arr == 1) ? g_k : g_v);
    float4 s = make_float4(0.f, 0.f, 0.f, 0.f);
#pragma unroll
    for (int p = 0; p < KSPLIT; p++) {
        float4 t = *(const float4*)&src[(size_t)p * (RCAP * E_DIM) + base];
        s.x += t.x; s.y += t.y; s.z += t.z; s.w += t.w;
    }
    *(float4*)&dst[base] = s;
}

// ---------------- dot: q row (smem) . k row (smem), 64 dims, f32x2 ----------------
__device__ __forceinline__ float dot64(const float* qrow, const float* krow) {
    const ulonglong2* qp = (const ulonglong2*)qrow;
    const ulonglong2* kp = (const ulonglong2*)krow;
    unsigned long long s01 = 0ULL, s23 = 0ULL;
#pragma unroll
    for (int d4 = 0; d4 < 16; d4++) {
        ulonglong2 qv = qp[d4];
        ulonglong2 kv = kp[d4];
        ffma2(s01, qv.x, kv.x);
        ffma2(s23, qv.y, kv.y);
    }
    float e0, e1, e2, e3;
    upk2(s01, e0, e1); upk2(s23, e2, e3);
    return (e0 + e1) + (e2 + e3);
}

// ---------------- K3: per-head attention column sums ----------------
// grid (NHEADS, 8 row-blocks), 256 threads (8 warps, one row per warp per group)
__global__ void __launch_bounds__(256) k_attn() {
    extern __shared__ float sm[];
    float* kbuf  = sm;                    // [128][KBSTR]
    float* qr    = kbuf + 128 * KBSTR;    // [8][KBSTR]
    float* c_sm  = qr + 8 * KBSTR;        // [S_LEN]
    float* w0p   = c_sm + S_LEN;          // [1]

    int h = blockIdx.x, rb = blockIdx.y, ns = g_ns;
    int tid = threadIdx.x, w = tid >> 5, lane = tid & 31;
    int zc = S_LEN - ns;
    const float* qh = g_q + h * HD;
    const float* kh = g_k + h * HD;

    if (tid == 0) *w0p = 0.f;
    for (int i = tid; i < ns; i += 256) c_sm[i] = 0.f;

    if (ns <= 128) {
        // ---------- fast static path ----------
        // load all k rows into smem (float4, coalesced)
        for (int idx = tid; idx < ns * 16; idx += 256) {
            int j = idx >> 4, d4 = idx & 15;
            *(float4*)&kbuf[j * KBSTR + 4 * d4] =
                *(const float4*)&kh[(size_t)j * E_DIM + 4 * d4];
        }
        __syncthreads();
        int ngroups = (ns + 63) >> 6;
        for (int g = 0; g < ngroups; g++) {
            int i = g * 64 + rb * 8 + w;
            bool active = (i < ns);
            if (active && lane < 16)
                *(float4*)&qr[w * KBSTR + 4 * lane] =
                    *(const float4*)&qh[(size_t)i * E_DIM + 4 * lane];
            __syncwarp();
            float sreg[4];
            float m = -1e30f;
            if (active) {
#pragma unroll
                for (int t = 0; t < 4; t++) {
                    int j = t * 32 + lane;
                    sreg[t] = (j < ns) ? dot64(&qr[w * KBSTR], &kbuf[j * KBSTR]) : -1e30f;
                    m = fmaxf(m, sreg[t]);
                }
#pragma unroll
                for (int o = 16; o > 0; o >>= 1)
                    m = fmaxf(m, __shfl_xor_sync(0xffffffffu, m, o));
                if (zc > 0) m = fmaxf(m, 0.f);       // masked entries are ZERO, not -inf
                float e[4];
                float Z = 0.f;
#pragma unroll
                for (int t = 0; t < 4; t++) {
                    int j = t * 32 + lane;
                    e[t] = (j < ns) ? __expf(sreg[t] - m) : 0.f;
                    Z += e[t];
                }
#pragma unroll
                for (int o = 16; o > 0; o >>= 1)
                    Z += __shfl_xor_sync(0xffffffffu, Z, o);
                Z += (float)zc * __expf(-m);
                float invZ = 1.f / Z;
#pragma unroll
                for (int t = 0; t < 4; t++) {
                    int j = t * 32 + lane;
                    if (j < ns) atomicAdd(&c_sm[j], e[t] * invZ);
                }
                if (lane == 0) atomicAdd(w0p, __expf(-m) * invZ);
            }
        }
    } else {
        // ---------- general chunked path (ns > 128, effectively never) ----------
        const int JT = 128;
        __shared__ int s_loaded;
        if (tid == 0) s_loaded = -1;
        __syncthreads();
        int nchunks = (ns + JT - 1) / JT;
        int ngroups = (ns + 63) / 64;
        for (int g = 0; g < ngroups; g++) {
            int i = g * 64 + rb * 8 + w;
            bool active = (i < ns);
            if (active && lane < 16)
                *(float4*)&qr[w * KBSTR + 4 * lane] =
                    *(const float4*)&qh[(size_t)i * E_DIM + 4 * lane];
            __syncwarp();
            float m = -1e30f, Z = 0.f;
            for (int c = 0; c < nchunks; c++) {
                int c0 = c * JT, cl = min(JT, ns - c0);
                if (s_loaded != c) {
                    __syncthreads();
                    for (int idx = tid; idx < cl * 16; idx += 256) {
                        int j = idx >> 4, d4 = idx & 15;
                        *(float4*)&kbuf[j * KBSTR + 4 * d4] =
                            *(const float4*)&kh[(size_t)(c0 + j) * E_DIM + 4 * d4];
                    }
                    if (tid == 0) s_loaded = c;
                    __syncthreads();
                }
                if (active)
                    for (int j = lane; j < cl; j += 32) {
                        float s = dot64(&qr[w * KBSTR], &kbuf[j * KBSTR]);
                        float mn = fmaxf(m, s);
                        Z = Z * __expf(m - mn) + __expf(s - mn);
                        m = mn;
                    }
            }
            float mrow = 0.f, invZ = 0.f;
            if (active) {
                mrow = m;
#pragma unroll
                for (int o = 16; o > 0; o >>= 1)
                    mrow = fmaxf(mrow, __shfl_xor_sync(0xffffffffu, mrow, o));
                if (zc > 0) mrow = fmaxf(mrow, 0.f);
                float z = Z * __expf(m - mrow);
#pragma unroll
                for (int o = 16; o > 0; o >>= 1)
                    z += __shfl_xor_sync(0xffffffffu, z, o);
                z += (float)zc * __expf(-mrow);
                invZ = 1.f / z;
            }
            for (int c = 0; c < nchunks; c++) {
                int c0 = c * JT, cl = min(JT, ns - c0);
                if (s_loaded != c) {
                    __syncthreads();
                    for (int idx = tid; idx < cl * 16; idx += 256) {
                        int j = idx >> 4, d4 = idx & 15;
                        *(float4*)&kbuf[j * KBSTR + 4 * d4] =
                            *(const float4*)&kh[(size_t)(c0 + j) * E_DIM + 4 * d4];
                    }
                    if (tid == 0) s_loaded = c;
                    __syncthreads();
                }
                if (active)
                    for (int j = lane; j < cl; j += 32) {
                        float s = dot64(&qr[w * KBSTR], &kbuf[j * KBSTR]);
                        atomicAdd(&c_sm[c0 + j], __expf(s - mrow) * invZ);
                    }
            }
            if (active && lane == 0) atomicAdd(w0p, __expf(-mrow) * invZ);
        }
    }
    __syncthreads();
    // flush block-local sums to global
    for (int j = tid; j < ns; j += 256) atomicAdd(&g_c[h * S_LEN + j], c_sm[j]);
    if (tid == 0) atomicAdd(&g_w0[h], *w0p);
}

// ---------------- K3b: att[h,d] from c, w0, V ----------------
// grid (NHEADS), 256 threads (4 j-parts x 64 dims)
__global__ void __launch_bounds__(256) k_att2() {
    __shared__ float red[4][64];
    int h = blockIdx.x, ns = g_ns;
    int tid = threadIdx.x;
    int d = tid & 63, part = tid >> 6;
    float w0 = g_w0[h];
    float a0 = 0.f, a1 = 0.f;
    int j = part;
    for (; j + 4 < ns; j += 8) {
        a0 += (g_c[h * S_LEN + j]     - w0) * g_v[(size_t)j       * E_DIM + h * HD + d];
        a1 += (g_c[h * S_LEN + j + 4] - w0) * g_v[(size_t)(j + 4) * E_DIM + h * HD + d];
    }
    for (; j < ns; j += 4)
        a0 += (g_c[h * S_LEN + j] - w0) * g_v[(size_t)j * E_DIM + h * HD + d];
    red[part][d] = a0 + a1;
    __syncthreads();
    if (tid < 64) {
        float tot = red[0][d] + red[1][d] + red[2][d] + red[3][d]
                  + w0 * g_v[(size_t)ns * E_DIM + h * HD + d];   // vtot row
        g_att[h * HD + d] = tot / (float)ns;
    }
}

// ---------------- K4: final vecmat out = att @ Wo + bo (split-K x32) ----------------
__global__ void __launch_bounds__(256) k_out(const float* __restrict__ Wo,
                                             const float* __restrict__ bo,
                                             float* __restrict__ dout) {
    int ky = blockIdx.y;
    int k0 = ky * 32;
    __shared__ float a_s[32];
    if (threadIdx.x < 32) a_s[threadIdx.x] = g_att[k0 + threadIdx.x];
    __syncthreads();
    int c = blockIdx.x * 256 + threadIdx.x;
    float acc = (ky == 0) ? bo[c] : 0.f;
#pragma unroll
    for (int kk = 0; kk < 32; kk++)
        acc += a_s[kk] * Wo[(size_t)(k0 + kk) * E_DIM + c];
    atomicAdd(&dout[c], acc);
}

// ---------------- launch ----------------
#define PROJ_SMEM ((64 * ASTR + 64 * 128) * 4)
#define ATTN_SMEM ((128 * KBSTR + 8 * KBSTR + S_LEN + 8) * 4)

extern "C" void kernel_launch(void* const* d_in, const int* in_sizes, int n_in,
                              void* d_out, int out_size) {
    const float* x   = (const float*)d_in[0];
    const int*   seg = (const int*)d_in[1];
    const int*   pos = (const int*)d_in[2];
    const float* Wq = (const float*)d_in[3];
    const float* bq = (const float*)d_in[4];
    const float* Wk = (const float*)d_in[5];
    const float* bk = (const float*)d_in[6];
    const float* Wv = (const float*)d_in[7];
    const float* bv = (const float*)d_in[8];
    const float* Wo = (const float*)d_in[9];
    const float* bo = (const float*)d_in[10];
    float* out = (float*)d_out;

    cudaFuncSetAttribute(k_proj, cudaFuncAttributeMaxDynamicSharedMemorySize, PROJ_SMEM);
    cudaFuncSetAttribute(k_attn, cudaFuncAttributeMaxDynamicSharedMemorySize, ATTN_SMEM);

    k_pre<<<dim3(4, XS), 256>>>(x, seg, pos, out);
    k_proj<<<dim3(8, KSPLIT, 3), 256, PROJ_SMEM>>>(x, Wq, Wk, Wv, bq, bk, bv);
    k_reduce<<<dim3(RCAP, 3), 256>>>();
    k_attn<<<dim3(NHEADS, 8), 256, ATTN_SMEM>>>();
    k_att2<<<NHEADS, 256>>>();
    k_out<<<dim3(4, 32), 256>>>(Wo, bo, out);
}

// round 9
// speedup vs baseline: 1.4175x; 1.0552x over previous
#include <cuda_runtime.h>

#define S_LEN   2048
#define E_DIM   1024
#define NHEADS  16
#define HD      64
#define MAXR    2049   // ns rows + 1 virtual row (xsum -> vtot)
#define KSPLIT  16     // proj K-splits (64 k each)
#define RCAP    128    // rows covered by the split partial-buffer path
#define XS      32     // colsum row splits
#define ASTR    260    // proj A-dup smem row stride (floats)
#define KBSTR   68     // attn smem row stride (floats); 68/4=17 odd -> conflict-free float4

// ---------------- device scratch (static, no runtime allocation) ----------------
__device__ int   g_lo, g_ns;
__device__ float g_xsump[XS][E_DIM];
__device__ float g_qp[KSPLIT][RCAP * E_DIM];
__device__ float g_kp[KSPLIT][RCAP * E_DIM];
__device__ float g_vp[KSPLIT][RCAP * E_DIM];
__device__ float g_q[MAXR * E_DIM];
__device__ float g_k[MAXR * E_DIM];
__device__ float g_v[MAXR * E_DIM];   // row ns = vtot
__device__ float g_c[NHEADS * S_LEN]; // per-head softmax column sums
__device__ float g_w0[NHEADS];

// ---------------- f32x2 packed helpers ----------------
__device__ __forceinline__ void upk2(unsigned long long v, float& lo, float& hi) {
    asm("mov.b64 {%0,%1}, %2;" : "=f"(lo), "=f"(hi) : "l"(v));
}
__device__ __forceinline__ void ffma2(unsigned long long& d, unsigned long long a,
                                      unsigned long long b) {
    asm("fma.rn.f32x2 %0, %1, %2, %0;" : "+l"(d) : "l"(a), "l"(b));
}

// ---------------- K0: colsum partials + bounds + zero scratch ----------------
// grid (4, XS=32) = 128 blocks, 256 threads
__global__ void __launch_bounds__(256) k_pre(const float* __restrict__ x,
                                             const int* __restrict__ seg,
                                             const int* __restrict__ pos,
                                             float* __restrict__ dout) {
    int bx = blockIdx.x, by = blockIdx.y;
    int tid = threadIdx.x;
    int c  = bx * 256 + tid;
    int r0 = by * (S_LEN / XS);
    float a = 0.f;
#pragma unroll 16
    for (int r = r0; r < r0 + S_LEN / XS; ++r) a += x[(size_t)r * E_DIM + c];
    g_xsump[by][c] = a;
    int lb = by * 4 + bx;                        // 0..127
    g_c[lb * 256 + tid] = 0.f;                   // covers NHEADS*S_LEN = 32768
    if (by == 0) dout[bx * 256 + tid] = 0.f;
    if (lb == 0 && tid < NHEADS) g_w0[tid] = 0.f;
    if (lb == 0) {
        __shared__ int s_lo, s_cnt, s_t;
        if (tid == 0) { s_t = seg[pos[0]]; s_lo = 0; s_cnt = 0; }
        __syncthreads();
        int t = s_t, lo = 0, cnt = 0;
        for (int i = tid; i < S_LEN; i += 256) {
            int v = seg[i];
            lo  += (v <  t);
            cnt += (v == t);
        }
        atomicAdd(&s_lo, lo);
        atomicAdd(&s_cnt, cnt);
        __syncthreads();
        if (tid == 0) { g_lo = s_lo; g_ns = s_cnt; }
    }
}

// ---------------- proj helpers ----------------
__device__ __forceinline__ float4 proj_ldA(const float* __restrict__ x,
                                           int lo, int ns, int mat, int gr, int kidx) {
    if (gr < ns) return *(const float4*)&x[(size_t)(lo + gr) * E_DIM + kidx];
    if (gr == ns && mat == 2) {
        float4 s = make_float4(0.f, 0.f, 0.f, 0.f);
#pragma unroll
        for (int p = 0; p < XS; p++) {
            float4 t = *(const float4*)&g_xsump[p][kidx];
            s.x += t.x; s.y += t.y; s.z += t.z; s.w += t.w;
        }
        return s;
    }
    return make_float4(0.f, 0.f, 0.f, 0.f);
}

// tile worker: M = 8*R rows, N = 128 cols, K = 64 (one split), full preload
template<int R>
__device__ __forceinline__ void proj_run(
    const float* __restrict__ x, const float* __restrict__ W,
    const float* __restrict__ bias, float* __restrict__ outp,
    int lo, int ns, int nrows, int mat, int kbase, bool addBias,
    float* As_d, float* Bs, int colbase)
{
    int tid = threadIdx.x;
    int tx = tid & 31, ty = tid >> 5;
#pragma unroll
    for (int u = 0; u < 8; u++) {
        int idx = tid + 256 * u;
        int r = idx >> 5, c4 = idx & 31;
        *(float4*)&Bs[r * 128 + c4 * 4] =
            *(const float4*)&W[(size_t)(kbase + r) * E_DIM + colbase + c4 * 4];
    }
#pragma unroll
    for (int u = 0; u < R / 2; u++) {
        int idx = tid + 256 * u;
        int r = idx >> 4, k4 = idx & 15;
        float4 v = proj_ldA(x, lo, ns, mat, r, kbase + 4 * k4);
        float vv[4] = {v.x, v.y, v.z, v.w};
#pragma unroll
        for (int i = 0; i < 4; i++) {
            float2 d2; d2.x = vv[i]; d2.y = vv[i];
            *(float2*)&As_d[(4 * k4 + i) * ASTR + 2 * r] = d2;
        }
    }
    __syncthreads();

    unsigned long long acc[R][2];
#pragma unroll
    for (int r = 0; r < R; r++) { acc[r][0] = 0ULL; acc[r][1] = 0ULL; }

#pragma unroll 4
    for (int kk = 0; kk < 64; kk++) {
        const ulonglong2* ap = (const ulonglong2*)&As_d[kk * ASTR + 2 * R * ty];
        unsigned long long b0 = *(const unsigned long long*)&Bs[kk * 128 + 2 * tx];
        unsigned long long b1 = *(const unsigned long long*)&Bs[kk * 128 + 2 * tx + 64];
#pragma unroll
        for (int q = 0; q < R / 2; q++) {
            ulonglong2 t = ap[q];
            ffma2(acc[2 * q][0],     t.x, b0); ffma2(acc[2 * q][1],     t.x, b1);
            ffma2(acc[2 * q + 1][0], t.y, b0); ffma2(acc[2 * q + 1][1], t.y, b1);
        }
    }
#pragma unroll
    for (int r = 0; r < R; r++) {
        int gr = R * ty + r;
        if (gr >= nrows) continue;
        bool virt = (gr == ns) && (mat == 2);
#pragma unroll
        for (int p = 0; p < 2; p++) {
            float v0, v1;
            upk2(acc[r][p], v0, v1);
            int c0 = colbase + 2 * tx + 64 * p;
            if (addBias) {
                float sc = virt ? (float)S_LEN : 1.f;
                v0 += sc * bias[c0];
                v1 += sc * bias[c0 + 1];
            }
            float2 st2; st2.x = v0; st2.y = v1;
            *(float2*)&outp[(size_t)gr * E_DIM + c0] = st2;
        }
    }
}

// ---------------- K2: projections (split-K into partial buffers) ----------------
__global__ void __launch_bounds__(256) k_proj(
    const float* __restrict__ x,
    const float* __restrict__ W0, const float* __restrict__ W1,
    const float* __restrict__ W2,
    const float* __restrict__ b0, const float* __restrict__ b1,
    const float* __restrict__ b2) {
    extern __shared__ float sm[];
    float* As_d = sm;               // [64][ASTR]
    float* Bs   = sm + 64 * ASTR;   // [64][128]
    int mat = blockIdx.z, kb = blockIdx.y;
    int ns = g_ns, lo = g_lo;
    int nrows = ns + (mat == 2 ? 1 : 0);
    const float* W    = (mat == 0) ? W0 : ((mat == 1) ? W1 : W2);
    const float* bias = (mat == 0) ? b0 : ((mat == 1) ? b1 : b2);
    float* partial = (mat == 0) ? g_qp[kb] : ((mat == 1) ? g_kp[kb] : g_vp[kb]);
    float* dense   = (mat == 0) ? g_q : ((mat == 1) ? g_k : g_v);
    int colbase = blockIdx.x * 128;
    int kbase = kb * 64;
    int mrows = min(nrows, RCAP);

    if      (mrows <= 64) proj_run<8>(x, W, bias, partial, lo, ns, mrows, mat, kbase, kb == 0, As_d, Bs, colbase);
    else if (mrows <= 80) proj_run<10>(x, W, bias, partial, lo, ns, mrows, mat, kbase, kb == 0, As_d, Bs, colbase);
    else if (mrows <= 96) proj_run<12>(x, W, bias, partial, lo, ns, mrows, mat, kbase, kb == 0, As_d, Bs, colbase);
    else                  proj_run<16>(x, W, bias, partial, lo, ns, mrows, mat, kbase, kb == 0, As_d, Bs, colbase);

    if (nrows > RCAP && kb == 0) {
        for (int idx = threadIdx.x; idx < (nrows - RCAP) * 128; idx += 256) {
            int r = RCAP + idx / 128, c = colbase + (idx & 127);
            float acc = bias[c] * ((r == ns && mat == 2) ? (float)S_LEN : 1.f);
            for (int k = 0; k < E_DIM; k++) {
                float xv;
                if (r < ns) xv = x[(size_t)(lo + r) * E_DIM + k];
                else { xv = 0.f; for (int p = 0; p < XS; p++) xv += g_xsump[p][k]; }
                acc += xv * W[(size_t)k * E_DIM + c];
            }
            dense[(size_t)r * E_DIM + c] = acc;
        }
    }
}

// ---------------- K2b: sum split-K partials (float4, high MLP) ----------------
__global__ void __launch_bounds__(256) k_reduce() {
    int ns = g_ns;
    int total = min(ns + 1, RCAP) * E_DIM;
    int base = blockIdx.x * 1024 + threadIdx.x * 4;
    if (base >= total) return;
    int arr = blockIdx.y;
    const float* src = (arr == 0) ? &g_qp[0][0] : ((arr == 1) ? &g_kp[0][0] : &g_vp[0][0]);
    float* dst = (arr == 0) ? g_q : ((arr == 1) ? g_k : g_v);
    float4 s = make_float4(0.f, 0.f, 0.f, 0.f);
#pragma unroll
    for (int p = 0; p < KSPLIT; p++) {
        float4 t = *(const float4*)&src[(size_t)p * (RCAP * E_DIM) + base];
        s.x += t.x; s.y += t.y; s.z += t.z; s.w += t.w;
    }
    *(float4*)&dst[base] = s;
}

// ---------------- dot: q row (smem) . k row (smem), 64 dims, f32x2 ----------------
__device__ __forceinline__ float dot64(const float* qrow, const float* krow) {
    const ulonglong2* qp = (const ulonglong2*)qrow;
    const ulonglong2* kp = (const ulonglong2*)krow;
    unsigned long long s01 = 0ULL, s23 = 0ULL;
#pragma unroll
    for (int d4 = 0; d4 < 16; d4++) {
        ulonglong2 qv = qp[d4];
        ulonglong2 kv = kp[d4];
        ffma2(s01, qv.x, kv.x);
        ffma2(s23, qv.y, kv.y);
    }
    float e0, e1, e2, e3;
    upk2(s01, e0, e1); upk2(s23, e2, e3);
    return (e0 + e1) + (e2 + e3);
}

// ---------------- K3: per-head attention column sums (direct REDG out) ----------------
// grid (NHEADS, 8 row-blocks), 256 threads (8 warps, one row per warp per group)
__global__ void __launch_bounds__(256) k_attn() {
    extern __shared__ float sm[];
    float* kbuf = sm;                    // [128][KBSTR]
    float* qr   = kbuf + 128 * KBSTR;    // [8][KBSTR]

    int h = blockIdx.x, rb = blockIdx.y, ns = g_ns;
    int tid = threadIdx.x, w = tid >> 5, lane = tid & 31;
    int zc = S_LEN - ns;
    const float* qh = g_q + h * HD;
    const float* kh = g_k + h * HD;
    float* cg = g_c + h * S_LEN;

    if (ns <= 128) {
        // ---------- fast static path ----------
        for (int idx = tid; idx < ns * 16; idx += 256) {
            int j = idx >> 4, d4 = idx & 15;
            *(float4*)&kbuf[j * KBSTR + 4 * d4] =
                *(const float4*)&kh[(size_t)j * E_DIM + 4 * d4];
        }
        __syncthreads();
        int ngroups = (ns + 63) >> 6;
        for (int g = 0; g < ngroups; g++) {
            int i = g * 64 + rb * 8 + w;
            bool active = (i < ns);
            if (active && lane < 16)
                *(float4*)&qr[w * KBSTR + 4 * lane] =
                    *(const float4*)&qh[(size_t)i * E_DIM + 4 * lane];
            __syncwarp();
            if (active) {
                float sreg[4];
                float m = -1e30f;
                int nt = (ns + 31) >> 5;          // warp-uniform dot count
#pragma unroll
                for (int t = 0; t < 4; t++) {
                    if (t >= nt) break;
                    int j = t * 32 + lane;
                    int jj = (j < ns) ? j : (ns - 1);   // clamp: safe smem read
                    float s = dot64(&qr[w * KBSTR], &kbuf[jj * KBSTR]);
                    sreg[t] = (j < ns) ? s : -1e30f;
                    m = fmaxf(m, sreg[t]);
                }
#pragma unroll
                for (int o = 16; o > 0; o >>= 1)
                    m = fmaxf(m, __shfl_xor_sync(0xffffffffu, m, o));
                if (zc > 0) m = fmaxf(m, 0.f);    // masked entries are ZERO, not -inf
                float e[4];
                float Z = 0.f;
#pragma unroll
                for (int t = 0; t < 4; t++) {
                    if (t >= nt) break;
                    int j = t * 32 + lane;
                    e[t] = (j < ns) ? __expf(sreg[t] - m) : 0.f;
                    Z += e[t];
                }
#pragma unroll
                for (int o = 16; o > 0; o >>= 1)
                    Z += __shfl_xor_sync(0xffffffffu, Z, o);
                Z += (float)zc * __expf(-m);
                float invZ = 1.f / Z;
#pragma unroll
                for (int t = 0; t < 4; t++) {
                    if (t >= nt) break;
                    int j = t * 32 + lane;
                    if (j < ns) atomicAdd(&cg[j], e[t] * invZ);   // REDG
                }
                if (lane == 0) atomicAdd(&g_w0[h], __expf(-m) * invZ);
            }
        }
    } else {
        // ---------- general chunked path (ns > 128, effectively never) ----------
        const int JT = 128;
        __shared__ int s_loaded;
        if (tid == 0) s_loaded = -1;
        __syncthreads();
        int nchunks = (ns + JT - 1) / JT;
        int ngroups = (ns + 63) / 64;
        for (int g = 0; g < ngroups; g++) {
            int i = g * 64 + rb * 8 + w;
            bool active = (i < ns);
            if (active && lane < 16)
                *(float4*)&qr[w * KBSTR + 4 * lane] =
                    *(const float4*)&qh[(size_t)i * E_DIM + 4 * lane];
            __syncwarp();
            float m = -1e30f, Z = 0.f;
            for (int c = 0; c < nchunks; c++) {
                int c0 = c * JT, cl = min(JT, ns - c0);
                if (s_loaded != c) {
                    __syncthreads();
                    for (int idx = tid; idx < cl * 16; idx += 256) {
                        int j = idx >> 4, d4 = idx & 15;
                        *(float4*)&kbuf[j * KBSTR + 4 * d4] =
                            *(const float4*)&kh[(size_t)(c0 + j) * E_DIM + 4 * d4];
                    }
                    if (tid == 0) s_loaded = c;
                    __syncthreads();
                }
                if (active)
                    for (int j = lane; j < cl; j += 32) {
                        float s = dot64(&qr[w * KBSTR], &kbuf[j * KBSTR]);
                        float mn = fmaxf(m, s);
                        Z = Z * __expf(m - mn) + __expf(s - mn);
                        m = mn;
                    }
            }
            float mrow = 0.f, invZ = 0.f;
            if (active) {
                mrow = m;
#pragma unroll
                for (int o = 16; o > 0; o >>= 1)
                    mrow = fmaxf(mrow, __shfl_xor_sync(0xffffffffu, mrow, o));
                if (zc > 0) mrow = fmaxf(mrow, 0.f);
                float z = Z * __expf(m - mrow);
#pragma unroll
                for (int o = 16; o > 0; o >>= 1)
                    z += __shfl_xor_sync(0xffffffffu, z, o);
                z += (float)zc * __expf(-mrow);
                invZ = 1.f / z;
            }
            for (int c = 0; c < nchunks; c++) {
                int c0 = c * JT, cl = min(JT, ns - c0);
                if (s_loaded != c) {
                    __syncthreads();
                    for (int idx = tid; idx < cl * 16; idx += 256) {
                        int j = idx >> 4, d4 = idx & 15;
                        *(float4*)&kbuf[j * KBSTR + 4 * d4] =
                            *(const float4*)&kh[(size_t)(c0 + j) * E_DIM + 4 * d4];
                    }
                    if (tid == 0) s_loaded = c;
                    __syncthreads();
                }
                if (active)
                    for (int j = lane; j < cl; j += 32) {
                        float s = dot64(&qr[w * KBSTR], &kbuf[j * KBSTR]);
                        atomicAdd(&cg[c0 + j], __expf(s - mrow) * invZ);
                    }
            }
            if (active && lane == 0) atomicAdd(&g_w0[h], __expf(-mrow) * invZ);
        }
    }
}

// ---------------- K4: att slice from c/w0/V, then vecmat out = att @ Wo + bo ----------------
// grid (4 coltiles of 256, 32 kslices of 32), 256 threads
__global__ void __launch_bounds__(256) k_out(const float* __restrict__ Wo,
                                             const float* __restrict__ bo,
                                             float* __restrict__ dout) {
    __shared__ float c_s[S_LEN];
    __shared__ float red[8][32];
    __shared__ float att_s[32];
    int ky = blockIdx.y;
    int k0 = ky * 32;             // global att-dim base
    int h  = ky >> 1;             // owning head
    int ns = g_ns;
    int tid = threadIdx.x;
    int d = tid & 31, part = tid >> 5;   // 8 j-parts x 32 dims
    float w0 = g_w0[h];

    for (int i = tid; i < ns; i += 256) c_s[i] = g_c[h * S_LEN + i];
    __syncthreads();

    {
        float a0 = 0.f, a1 = 0.f;
        int j = part;
        for (; j + 8 < ns; j += 16) {
            a0 += (c_s[j]     - w0) * g_v[(size_t)j       * E_DIM + k0 + d];
            a1 += (c_s[j + 8] - w0) * g_v[(size_t)(j + 8) * E_DIM + k0 + d];
        }
        for (; j < ns; j += 8)
            a0 += (c_s[j] - w0) * g_v[(size_t)j * E_DIM + k0 + d];
        red[part][d] = a0 + a1;
    }
    __syncthreads();
    if (tid < 32) {
        float tot = red[0][d] + red[1][d] + red[2][d] + red[3][d]
                  + red[4][d] + red[5][d] + red[6][d] + red[7][d]
                  + w0 * g_v[(size_t)ns * E_DIM + k0 + d];   // vtot row
        att_s[d] = tot / (float)ns;
    }
    __syncthreads();

    int c = blockIdx.x * 256 + tid;
    float acc = (ky == 0) ? bo[c] : 0.f;
#pragma unroll
    for (int kk = 0; kk < 32; kk++)
        acc += att_s[kk] * Wo[(size_t)(k0 + kk) * E_DIM + c];
    atomicAdd(&dout[c], acc);
}

// ---------------- launch ----------------
#define PROJ_SMEM ((64 * ASTR + 64 * 128) * 4)
#define ATTN_SMEM ((128 * KBSTR + 8 * KBSTR) * 4)

extern "C" void kernel_launch(void* const* d_in, const int* in_sizes, int n_in,
                              void* d_out, int out_size) {
    const float* x   = (const float*)d_in[0];
    const int*   seg = (const int*)d_in[1];
    const int*   pos = (const int*)d_in[2];
    const float* Wq = (const float*)d_in[3];
    const float* bq = (const float*)d_in[4];
    const float* Wk = (const float*)d_in[5];
    const float* bk = (const float*)d_in[6];
    const float* Wv = (const float*)d_in[7];
    const float* bv = (const float*)d_in[8];
    const float* Wo = (const float*)d_in[9];
    const float* bo = (const float*)d_in[10];
    float* out = (float*)d_out;

    cudaFuncSetAttribute(k_proj, cudaFuncAttributeMaxDynamicSharedMemorySize, PROJ_SMEM);
    cudaFuncSetAttribute(k_attn, cudaFuncAttributeMaxDynamicSharedMemorySize, ATTN_SMEM);

    k_pre<<<dim3(4, XS), 256>>>(x, seg, pos, out);
    k_proj<<<dim3(8, KSPLIT, 3), 256, PROJ_SMEM>>>(x, Wq, Wk, Wv, bq, bk, bv);
    k_reduce<<<dim3(RCAP, 3), 256>>>();
    k_attn<<<dim3(NHEADS, 8), 256, ATTN_SMEM>>>();
    k_out<<<dim3(4, 32), 256>>>(Wo, bo, out);
}